// round 5
// baseline (speedup 1.0000x reference)
#include <cuda_runtime.h>
#include <math.h>

#define B_  4
#define S_  2048
#define H_  768
#define NH_ 12
#define HD_ 64

// Scratch for Q/K/V in [B, NH, S, HD] layout (25 MB each, 75 MB total).
__device__ float g_q[B_ * NH_ * S_ * HD_];
__device__ float g_k[B_ * NH_ * S_ * HD_];
__device__ float g_v[B_ * NH_ * S_ * HD_];

// ---------------------------------------------------------------------------
// Kernel 1: QKV projection.  out[b,h,s,d] = X[b,s,:] @ W[:, h*64+d] + bias
// Tiled GEMM: 64x64 output tile, K-step 16, 256 threads, 4x4 micro-tile.
// grid = (768/64=12, 8192/64=128, 3)   z selects {Q,K,V}.
// ---------------------------------------------------------------------------
__global__ __launch_bounds__(256) void qkv_kernel(
    const float* __restrict__ X,
    const float* __restrict__ Wq, const float* __restrict__ bq,
    const float* __restrict__ Wk, const float* __restrict__ bk,
    const float* __restrict__ Wv, const float* __restrict__ bv)
{
    __shared__ float Xs[16][65];   // [k][m], pad -> 2-way max on transpose store
    __shared__ float Ws[16][64];   // [k][n], row-major, float4 friendly

    const float* W; const float* bias; float* out;
    if (blockIdx.z == 0)      { W = Wq; bias = bq; out = g_q; }
    else if (blockIdx.z == 1) { W = Wk; bias = bk; out = g_k; }
    else                      { W = Wv; bias = bv; out = g_v; }

    const int tid = threadIdx.x;
    const int tx = tid & 15, ty = tid >> 4;
    const int mBase = blockIdx.y * 64;
    const int nBase = blockIdx.x * 64;

    // X tile loader: row = tid/4 (0..63), 4 consecutive k per thread
    const int xr  = tid >> 2;
    const int xk4 = (tid & 3) * 4;
    // W tile loader: k-row = tid/16 (0..15), 4 consecutive n per thread
    const int wr  = tid >> 4;
    const int wn4 = (tid & 15) * 4;

    const float* Xp = X + (size_t)(mBase + xr) * H_ + xk4;
    const float* Wp = W + (size_t)wr * H_ + nBase + wn4;

    float acc[4][4];
#pragma unroll
    for (int i = 0; i < 4; ++i)
#pragma unroll
        for (int j = 0; j < 4; ++j) acc[i][j] = 0.f;

    for (int k0 = 0; k0 < H_; k0 += 16) {
        float4 xv = *(const float4*)(Xp + k0);
        float4 wv = *(const float4*)(Wp + (size_t)k0 * H_);
        if (k0) __syncthreads();
        Xs[xk4 + 0][xr] = xv.x;
        Xs[xk4 + 1][xr] = xv.y;
        Xs[xk4 + 2][xr] = xv.z;
        Xs[xk4 + 3][xr] = xv.w;
        *(float4*)&Ws[wr][wn4] = wv;
        __syncthreads();
#pragma unroll
        for (int kk = 0; kk < 16; ++kk) {
            float a0 = Xs[kk][ty * 4 + 0];
            float a1 = Xs[kk][ty * 4 + 1];
            float a2 = Xs[kk][ty * 4 + 2];
            float a3 = Xs[kk][ty * 4 + 3];
            float4 b4 = *(float4*)&Ws[kk][tx * 4];
            acc[0][0] += a0 * b4.x; acc[0][1] += a0 * b4.y; acc[0][2] += a0 * b4.z; acc[0][3] += a0 * b4.w;
            acc[1][0] += a1 * b4.x; acc[1][1] += a1 * b4.y; acc[1][2] += a1 * b4.z; acc[1][3] += a1 * b4.w;
            acc[2][0] += a2 * b4.x; acc[2][1] += a2 * b4.y; acc[2][2] += a2 * b4.z; acc[2][3] += a2 * b4.w;
            acc[3][0] += a3 * b4.x; acc[3][1] += a3 * b4.y; acc[3][2] += a3 * b4.z; acc[3][3] += a3 * b4.w;
        }
    }

    // Epilogue: add bias, write into [b, h, s, d] layout (BN=64 == one head)
    const int b = mBase >> 11;          // S_ = 2048
    const int s0 = mBase & (S_ - 1);
    const int h = nBase >> 6;
    float4 bb = *(const float4*)&bias[nBase + tx * 4];
    float* outp = out + ((size_t)(b * NH_ + h) * S_ + s0 + ty * 4) * HD_ + tx * 4;
#pragma unroll
    for (int i = 0; i < 4; ++i) {
        float4 r;
        r.x = acc[i][0] + bb.x;
        r.y = acc[i][1] + bb.y;
        r.z = acc[i][2] + bb.z;
        r.w = acc[i][3] + bb.w;
        *(float4*)(outp + (size_t)i * HD_) = r;
    }
}

// ---------------------------------------------------------------------------
// Kernel 2: flash attention.  One CTA = 64 query rows of one (b,h) pair.
// grid = (S/64 = 32, B*NH = 48), 256 threads, 4x4 micro-tile on 64x64 tiles.
// Shared: Qs (row-major), KPs (K^T XOR-swizzled, reused for P), Vs (row-major).
// Exactly 48 KB static shared.
// ---------------------------------------------------------------------------
__global__ __launch_bounds__(256) void attn_kernel(
    const float* __restrict__ mask, float* __restrict__ out)
{
    __shared__ float Qs[64 * 64];
    __shared__ float KPs[64 * 64];
    __shared__ float Vs[64 * 64];

    const int tid = threadIdx.x;
    const int tx = tid & 15, ty = tid >> 4;
    const int qTile = blockIdx.x;
    const int bh = blockIdx.y;
    const int bIdx = bh / NH_;
    const int hIdx = bh % NH_;

    const float* qBase = g_q + ((size_t)bh * S_ + qTile * 64) * HD_;
    const float* kBase = g_k + (size_t)bh * S_ * HD_;
    const float* vBase = g_v + (size_t)bh * S_ * HD_;
    const float* mBase = mask + (size_t)bIdx * S_;

    // Load Q tile (contiguous 16 KB), pre-scaled by 1/sqrt(HD) = 0.125
#pragma unroll
    for (int e = tid * 4; e < 4096; e += 1024) {
        float4 v = *(const float4*)(qBase + e);
        v.x *= 0.125f; v.y *= 0.125f; v.z *= 0.125f; v.w *= 0.125f;
        *(float4*)&Qs[e] = v;
    }

    float m[4], l[4], o[4][4];
#pragma unroll
    for (int i = 0; i < 4; ++i) {
        m[i] = -1e30f; l[i] = 0.f;
#pragma unroll
        for (int j = 0; j < 4; ++j) o[i][j] = 0.f;
    }

    const int kc  = tid >> 2;        // K row (c) handled by this thread
    const int kd4 = (tid & 3) * 4;   // starting d within the row

    for (int t = 0; t < S_ / 64; ++t) {
        const float* kt = kBase + (size_t)t * 64 * HD_;
        const float* vt = vBase + (size_t)t * 64 * HD_;

        __syncthreads();   // previous tile's PV reads of KPs/Vs are done
        // K^T store with XOR swizzle: element (d,c) -> KPs[d*64 + (c ^ sw(d))]
        // sw(d) = ((d>>2)&7)<<3  => conflict-free scatter stores AND
        // conflict-free LDS.128 reads of 4 consecutive c per row d.
#pragma unroll
        for (int u = 0; u < 4; ++u) {
            const int d0 = kd4 + u * 16;
            float4 k4 = *(const float4*)(kt + kc * HD_ + d0);
            const int off = kc ^ (((d0 >> 2) & 7) << 3);
            KPs[(d0 + 0) * 64 + off] = k4.x;
            KPs[(d0 + 1) * 64 + off] = k4.y;
            KPs[(d0 + 2) * 64 + off] = k4.z;
            KPs[(d0 + 3) * 64 + off] = k4.w;
            float4 v4 = *(const float4*)(vt + tid * 4 + u * 1024);
            *(float4*)&Vs[tid * 4 + u * 1024] = v4;
        }
        __syncthreads();

        // ---- scores: S = Q K^T (already scaled) ----
        float s[4][4];
#pragma unroll
        for (int i = 0; i < 4; ++i)
#pragma unroll
            for (int j = 0; j < 4; ++j) s[i][j] = 0.f;

#pragma unroll 16
        for (int kk = 0; kk < 64; ++kk) {
            float a0 = Qs[(ty * 4 + 0) * 64 + kk];
            float a1 = Qs[(ty * 4 + 1) * 64 + kk];
            float a2 = Qs[(ty * 4 + 2) * 64 + kk];
            float a3 = Qs[(ty * 4 + 3) * 64 + kk];
            const int sw = ((kk >> 2) & 7) << 3;
            float4 b4 = *(float4*)&KPs[kk * 64 + ((tx * 4) ^ sw)];
            s[0][0] += a0 * b4.x; s[0][1] += a0 * b4.y; s[0][2] += a0 * b4.z; s[0][3] += a0 * b4.w;
            s[1][0] += a1 * b4.x; s[1][1] += a1 * b4.y; s[1][2] += a1 * b4.z; s[1][3] += a1 * b4.w;
            s[2][0] += a2 * b4.x; s[2][1] += a2 * b4.y; s[2][2] += a2 * b4.z; s[2][3] += a2 * b4.w;
            s[3][0] += a3 * b4.x; s[3][1] += a3 * b4.y; s[3][2] += a3 * b4.z; s[3][3] += a3 * b4.w;
        }

        // additive attention mask (zeros in this problem, kept for correctness)
        float4 mk = *(const float4*)(mBase + t * 64 + tx * 4);
#pragma unroll
        for (int i = 0; i < 4; ++i) {
            s[i][0] += mk.x; s[i][1] += mk.y; s[i][2] += mk.z; s[i][3] += mk.w;
        }

        // ---- online softmax (row groups of 16 lanes within warp halves) ----
#pragma unroll
        for (int i = 0; i < 4; ++i) {
            float mr = fmaxf(fmaxf(s[i][0], s[i][1]), fmaxf(s[i][2], s[i][3]));
            mr = fmaxf(mr, __shfl_xor_sync(0xffffffffu, mr, 8));
            mr = fmaxf(mr, __shfl_xor_sync(0xffffffffu, mr, 4));
            mr = fmaxf(mr, __shfl_xor_sync(0xffffffffu, mr, 2));
            mr = fmaxf(mr, __shfl_xor_sync(0xffffffffu, mr, 1));
            float mn = fmaxf(m[i], mr);
            float sc = __expf(m[i] - mn);
            m[i] = mn;
            s[i][0] = __expf(s[i][0] - mn);
            s[i][1] = __expf(s[i][1] - mn);
            s[i][2] = __expf(s[i][2] - mn);
            s[i][3] = __expf(s[i][3] - mn);
            float rs = s[i][0] + s[i][1] + s[i][2] + s[i][3];
            rs += __shfl_xor_sync(0xffffffffu, rs, 8);
            rs += __shfl_xor_sync(0xffffffffu, rs, 4);
            rs += __shfl_xor_sync(0xffffffffu, rs, 2);
            rs += __shfl_xor_sync(0xffffffffu, rs, 1);
            l[i] = l[i] * sc + rs;
            o[i][0] *= sc; o[i][1] *= sc; o[i][2] *= sc; o[i][3] *= sc;
        }

        __syncthreads();   // everyone done reading K from KPs
        // write P into KPs (row-major)
#pragma unroll
        for (int i = 0; i < 4; ++i) {
            float4 p4 = make_float4(s[i][0], s[i][1], s[i][2], s[i][3]);
            *(float4*)&KPs[(ty * 4 + i) * 64 + tx * 4] = p4;
        }
        __syncthreads();

        // ---- O += P V ----
#pragma unroll 16
        for (int c = 0; c < 64; ++c) {
            float p0 = KPs[(ty * 4 + 0) * 64 + c];
            float p1 = KPs[(ty * 4 + 1) * 64 + c];
            float p2 = KPs[(ty * 4 + 2) * 64 + c];
            float p3 = KPs[(ty * 4 + 3) * 64 + c];
            float4 v4 = *(float4*)&Vs[c * 64 + tx * 4];
            o[0][0] += p0 * v4.x; o[0][1] += p0 * v4.y; o[0][2] += p0 * v4.z; o[0][3] += p0 * v4.w;
            o[1][0] += p1 * v4.x; o[1][1] += p1 * v4.y; o[1][2] += p1 * v4.z; o[1][3] += p1 * v4.w;
            o[2][0] += p2 * v4.x; o[2][1] += p2 * v4.y; o[2][2] += p2 * v4.z; o[2][3] += p2 * v4.w;
            o[3][0] += p3 * v4.x; o[3][1] += p3 * v4.y; o[3][2] += p3 * v4.z; o[3][3] += p3 * v4.w;
        }
    }

    // Epilogue: out[b, s, h*64 + d] = O / l   (merge heads)
    float* op = out + ((size_t)bIdx * S_ + qTile * 64 + ty * 4) * H_ + hIdx * HD_ + tx * 4;
#pragma unroll
    for (int i = 0; i < 4; ++i) {
        float inv = 1.0f / l[i];
        float4 r = make_float4(o[i][0] * inv, o[i][1] * inv, o[i][2] * inv, o[i][3] * inv);
        *(float4*)(op + (size_t)i * H_) = r;
    }
}

// ---------------------------------------------------------------------------
extern "C" void kernel_launch(void* const* d_in, const int* in_sizes, int n_in,
                              void* d_out, int out_size)
{
    const float* X    = (const float*)d_in[0];  // hidden_states [4,2048,768]
    const float* mask = (const float*)d_in[1];  // attention_mask [4,1,1,2048]
    const float* Wq   = (const float*)d_in[2];
    const float* bq   = (const float*)d_in[3];
    const float* Wk   = (const float*)d_in[4];
    const float* bk   = (const float*)d_in[5];
    const float* Wv   = (const float*)d_in[6];
    const float* bv   = (const float*)d_in[7];
    float* out = (float*)d_out;

    (void)in_sizes; (void)n_in; (void)out_size;

    dim3 g1(H_ / 64, (B_ * S_) / 64, 3);       // (12, 128, 3)
    qkv_kernel<<<g1, 256>>>(X, Wq, bq, Wk, bk, Wv, bv);

    dim3 g2(S_ / 64, B_ * NH_);                // (32, 48)
    attn_kernel<<<g2, 256>>>(mask, out);
}

// round 6
// speedup vs baseline: 2.4862x; 2.4862x over previous
#include <cuda_runtime.h>
#include <math.h>

#define B_  4
#define S_  2048
#define H_  768
#define NH_ 12
#define HD_ 64

// Scratch for Q/K/V in [B, NH, S, HD] layout.
__device__ float g_q[B_ * NH_ * S_ * HD_];
__device__ float g_k[B_ * NH_ * S_ * HD_];
__device__ float g_v[B_ * NH_ * S_ * HD_];

// ---------------------------------------------------------------------------
// tf32 helpers
// ---------------------------------------------------------------------------
__device__ __forceinline__ unsigned f2tf(float f) {
    unsigned u;
    asm("cvt.rna.tf32.f32 %0, %1;" : "=r"(u) : "f"(f));
    return u;
}
__device__ __forceinline__ float f2tf_f(float f) { return __uint_as_float(f2tf(f)); }

// D += A(16x8 row) * B(8x8 col), tf32 in, fp32 accum
__device__ __forceinline__ void mma8(float* c, const unsigned* a, const unsigned* b) {
    asm volatile(
        "mma.sync.aligned.m16n8k8.row.col.f32.tf32.tf32.f32 "
        "{%0,%1,%2,%3}, {%4,%5,%6,%7}, {%8,%9}, {%0,%1,%2,%3};\n"
        : "+f"(c[0]), "+f"(c[1]), "+f"(c[2]), "+f"(c[3])
        : "r"(a[0]), "r"(a[1]), "r"(a[2]), "r"(a[3]), "r"(b[0]), "r"(b[1]));
}

// ---------------------------------------------------------------------------
// Kernel 1: QKV projection with tf32 mma.
// CTA: 128(m) x 64(n), k-chunks of 64. 8 warps; warp w owns rows 16w..16w+15,
// all 64 n-cols (8 n-frags). grid = (8192/128=64, 768/64=12, 3).
// Smem: Xs[128][68] + Ws[64][72] + bias[64]
// ---------------------------------------------------------------------------
#define XS_STR 68
#define WS_STR 72
#define QKV_SMEM ((128 * XS_STR + 64 * WS_STR + 64) * 4)

__global__ __launch_bounds__(256) void qkv_mma(
    const float* __restrict__ X,
    const float* __restrict__ Wq, const float* __restrict__ bq,
    const float* __restrict__ Wk, const float* __restrict__ bk,
    const float* __restrict__ Wv, const float* __restrict__ bv)
{
    extern __shared__ float sm[];
    float* Xs = sm;                      // 128 x 68
    float* Ws = sm + 128 * XS_STR;       // 64 x 72
    float* Bs = Ws + 64 * WS_STR;        // 64

    const float* W; const float* bias; float* out;
    if (blockIdx.z == 0)      { W = Wq; bias = bq; out = g_q; }
    else if (blockIdx.z == 1) { W = Wk; bias = bk; out = g_k; }
    else                      { W = Wv; bias = bv; out = g_v; }

    const int tid  = threadIdx.x;
    const int lane = tid & 31;
    const int wid  = tid >> 5;
    const int r    = lane >> 2;   // 0..7
    const int t    = lane & 3;    // 0..3
    const int mBase = blockIdx.x * 128;
    const int nBase = blockIdx.y * 64;

    if (tid < 16) {
        float4 b4 = *(const float4*)(bias + nBase + tid * 4);
        *(float4*)&Bs[tid * 4] = b4;
    }

    float acc[8][4];
#pragma unroll
    for (int nf = 0; nf < 8; ++nf)
#pragma unroll
        for (int j = 0; j < 4; ++j) acc[nf][j] = 0.f;

    for (int kt = 0; kt < 12; ++kt) {
        __syncthreads();
        // X tile 128x64 (row-major, tf32-rounded)
#pragma unroll
        for (int i = 0; i < 8; ++i) {
            int e = tid * 4 + i * 1024;
            int row = e >> 6, col = e & 63;
            float4 v = *(const float4*)(X + (size_t)(mBase + row) * H_ + kt * 64 + col);
            v.x = f2tf_f(v.x); v.y = f2tf_f(v.y); v.z = f2tf_f(v.z); v.w = f2tf_f(v.w);
            *(float4*)&Xs[row * XS_STR + col] = v;
        }
        // W tile 64x64 ([k][n], tf32-rounded)
#pragma unroll
        for (int i = 0; i < 4; ++i) {
            int e = tid * 4 + i * 1024;
            int row = e >> 6, col = e & 63;
            float4 v = *(const float4*)(W + (size_t)(kt * 64 + row) * H_ + nBase + col);
            v.x = f2tf_f(v.x); v.y = f2tf_f(v.y); v.z = f2tf_f(v.z); v.w = f2tf_f(v.w);
            *(float4*)&Ws[row * WS_STR + col] = v;
        }
        __syncthreads();

#pragma unroll
        for (int ks = 0; ks < 8; ++ks) {
            unsigned a[4];
            const int ar = wid * 16 + r;
            a[0] = __float_as_uint(Xs[(ar    ) * XS_STR + ks * 8 + t    ]);
            a[1] = __float_as_uint(Xs[(ar + 8) * XS_STR + ks * 8 + t    ]);
            a[2] = __float_as_uint(Xs[(ar    ) * XS_STR + ks * 8 + t + 4]);
            a[3] = __float_as_uint(Xs[(ar + 8) * XS_STR + ks * 8 + t + 4]);
#pragma unroll
            for (int nf = 0; nf < 8; ++nf) {
                unsigned b[2];
                b[0] = __float_as_uint(Ws[(ks * 8 + t    ) * WS_STR + nf * 8 + r]);
                b[1] = __float_as_uint(Ws[(ks * 8 + t + 4) * WS_STR + nf * 8 + r]);
                mma8(acc[nf], a, b);
            }
        }
    }

    // Epilogue: out[b, h=blockIdx.y, s, d] with bias
    const int h = blockIdx.y;
#pragma unroll
    for (int nf = 0; nf < 8; ++nf) {
#pragma unroll
        for (int half = 0; half < 2; ++half) {
            int row = mBase + wid * 16 + r + 8 * half;
            int b = row >> 11, s = row & (S_ - 1);
            int col = nf * 8 + 2 * t;
            float2 o;
            o.x = acc[nf][2 * half + 0] + Bs[col];
            o.y = acc[nf][2 * half + 1] + Bs[col + 1];
            *(float2*)(out + ((size_t)(b * NH_ + h) * S_ + s) * HD_ + col) = o;
        }
    }
}

// ---------------------------------------------------------------------------
// Kernel 2: flash attention with tf32 mma.
// CTA: 128 Q rows of one (b,h); 8 warps, warp w owns rows 16w..16w+15 x all
// 64 key cols. Q A-frags live in registers for all 32 KV tiles.
// Smem: Ks[64][68] + Vs[64][72] + Ps[8 warps][16][68] + msk[64]
// grid = (S/128=16, B*NH=48)
// ---------------------------------------------------------------------------
#define KS_STR 68
#define VS_STR 72
#define PS_STR 68
#define ATTN_SMEM ((64 * KS_STR + 64 * VS_STR + 8 * 16 * PS_STR + 64) * 4)

__global__ __launch_bounds__(256) void attn_mma(
    const float* __restrict__ mask, float* __restrict__ out)
{
    extern __shared__ float sm[];
    float* Ks = sm;                              // 64 x 68
    float* Vs = Ks + 64 * KS_STR;                // 64 x 72
    float* Ps = Vs + 64 * VS_STR;                // 8 x 16 x 68
    float* Ms = Ps + 8 * 16 * PS_STR;            // 64

    const int tid  = threadIdx.x;
    const int lane = tid & 31;
    const int wid  = tid >> 5;
    const int r    = lane >> 2;
    const int t    = lane & 3;
    const int qTile = blockIdx.x;
    const int bh   = blockIdx.y;
    const int bIdx = bh / NH_;
    const int hIdx = bh % NH_;

    // Q A-fragments in registers (pre-scaled by 1/sqrt(64) = 0.125)
    const float* qb = g_q + ((size_t)bh * S_ + qTile * 128 + wid * 16) * HD_;
    unsigned qa[8][4];
#pragma unroll
    for (int kf = 0; kf < 8; ++kf) {
        qa[kf][0] = f2tf(0.125f * __ldg(qb + (r    ) * HD_ + kf * 8 + t    ));
        qa[kf][1] = f2tf(0.125f * __ldg(qb + (r + 8) * HD_ + kf * 8 + t    ));
        qa[kf][2] = f2tf(0.125f * __ldg(qb + (r    ) * HD_ + kf * 8 + t + 4));
        qa[kf][3] = f2tf(0.125f * __ldg(qb + (r + 8) * HD_ + kf * 8 + t + 4));
    }

    float o[8][4];
#pragma unroll
    for (int nf = 0; nf < 8; ++nf)
#pragma unroll
        for (int j = 0; j < 4; ++j) o[nf][j] = 0.f;
    float mrow[2] = { -1e30f, -1e30f };
    float lrow[2] = { 0.f, 0.f };

    const float* kB = g_k + (size_t)bh * S_ * HD_;
    const float* vB = g_v + (size_t)bh * S_ * HD_;
    const float* mB = mask + (size_t)bIdx * S_;
    float* Pw = Ps + wid * (16 * PS_STR);

    for (int tt = 0; tt < S_ / 64; ++tt) {
        __syncthreads();   // prev tile PV reads done (also covers Pw WAR)
        const float* kt = kB + (size_t)tt * 64 * HD_;
        const float* vt = vB + (size_t)tt * 64 * HD_;
#pragma unroll
        for (int i = 0; i < 4; ++i) {
            int e = tid * 4 + i * 1024;
            int row = e >> 6, col = e & 63;
            float4 kv = *(const float4*)(kt + e);
            kv.x = f2tf_f(kv.x); kv.y = f2tf_f(kv.y); kv.z = f2tf_f(kv.z); kv.w = f2tf_f(kv.w);
            *(float4*)&Ks[row * KS_STR + col] = kv;
            float4 vv = *(const float4*)(vt + e);
            vv.x = f2tf_f(vv.x); vv.y = f2tf_f(vv.y); vv.z = f2tf_f(vv.z); vv.w = f2tf_f(vv.w);
            *(float4*)&Vs[row * VS_STR + col] = vv;
        }
        if (tid < 16) *(float4*)&Ms[tid * 4] = *(const float4*)(mB + tt * 64 + tid * 4);
        __syncthreads();

        // ---- S = Q K^T ----
        float sc[8][4];
#pragma unroll
        for (int nf = 0; nf < 8; ++nf)
#pragma unroll
            for (int j = 0; j < 4; ++j) sc[nf][j] = 0.f;

#pragma unroll
        for (int ks = 0; ks < 8; ++ks) {
#pragma unroll
            for (int nf = 0; nf < 8; ++nf) {
                unsigned b[2];
                b[0] = __float_as_uint(Ks[(nf * 8 + r) * KS_STR + ks * 8 + t    ]);
                b[1] = __float_as_uint(Ks[(nf * 8 + r) * KS_STR + ks * 8 + t + 4]);
                mma8(sc[nf], qa[ks], b);
            }
        }

        // mask add
#pragma unroll
        for (int nf = 0; nf < 8; ++nf) {
            float2 mk = *(float2*)&Ms[nf * 8 + 2 * t];
            sc[nf][0] += mk.x; sc[nf][1] += mk.y;
            sc[nf][2] += mk.x; sc[nf][3] += mk.y;
        }

        // ---- online softmax (rows r, r+8; reduce over 4 lanes sharing row) ----
#pragma unroll
        for (int half = 0; half < 2; ++half) {
            float mx = -1e30f;
#pragma unroll
            for (int nf = 0; nf < 8; ++nf)
                mx = fmaxf(mx, fmaxf(sc[nf][2 * half], sc[nf][2 * half + 1]));
            mx = fmaxf(mx, __shfl_xor_sync(0xffffffffu, mx, 1));
            mx = fmaxf(mx, __shfl_xor_sync(0xffffffffu, mx, 2));
            float mn = fmaxf(mrow[half], mx);
            float scale = __expf(mrow[half] - mn);
            mrow[half] = mn;
            float rs = 0.f;
#pragma unroll
            for (int nf = 0; nf < 8; ++nf) {
                float e0 = __expf(sc[nf][2 * half]     - mn);
                float e1 = __expf(sc[nf][2 * half + 1] - mn);
                sc[nf][2 * half] = e0; sc[nf][2 * half + 1] = e1;
                rs += e0 + e1;
            }
            rs += __shfl_xor_sync(0xffffffffu, rs, 1);
            rs += __shfl_xor_sync(0xffffffffu, rs, 2);
            lrow[half] = lrow[half] * scale + rs;
#pragma unroll
            for (int nf = 0; nf < 8; ++nf) {
                o[nf][2 * half] *= scale; o[nf][2 * half + 1] *= scale;
            }
        }

        // ---- P -> warp-private smem (tf32-rounded) ----
#pragma unroll
        for (int nf = 0; nf < 8; ++nf) {
#pragma unroll
            for (int half = 0; half < 2; ++half) {
                float2 p;
                p.x = f2tf_f(sc[nf][2 * half]);
                p.y = f2tf_f(sc[nf][2 * half + 1]);
                *(float2*)&Pw[(r + 8 * half) * PS_STR + nf * 8 + 2 * t] = p;
            }
        }
        __syncwarp();

        // ---- O += P V ----
#pragma unroll
        for (int ks = 0; ks < 8; ++ks) {
            unsigned pa[4];
            pa[0] = __float_as_uint(Pw[(r    ) * PS_STR + ks * 8 + t    ]);
            pa[1] = __float_as_uint(Pw[(r + 8) * PS_STR + ks * 8 + t    ]);
            pa[2] = __float_as_uint(Pw[(r    ) * PS_STR + ks * 8 + t + 4]);
            pa[3] = __float_as_uint(Pw[(r + 8) * PS_STR + ks * 8 + t + 4]);
#pragma unroll
            for (int nf = 0; nf < 8; ++nf) {
                unsigned b[2];
                b[0] = __float_as_uint(Vs[(ks * 8 + t    ) * VS_STR + nf * 8 + r]);
                b[1] = __float_as_uint(Vs[(ks * 8 + t + 4) * VS_STR + nf * 8 + r]);
                mma8(o[nf], pa, b);
            }
        }
    }

    // Epilogue: out[b, s, h*64 + d] = O / l
    float inv[2] = { 1.0f / lrow[0], 1.0f / lrow[1] };
#pragma unroll
    for (int nf = 0; nf < 8; ++nf) {
#pragma unroll
        for (int half = 0; half < 2; ++half) {
            int s = qTile * 128 + wid * 16 + r + 8 * half;
            int col = hIdx * HD_ + nf * 8 + 2 * t;
            float2 v;
            v.x = o[nf][2 * half]     * inv[half];
            v.y = o[nf][2 * half + 1] * inv[half];
            *(float2*)(out + ((size_t)bIdx * S_ + s) * H_ + col) = v;
        }
    }
}

// ---------------------------------------------------------------------------
extern "C" void kernel_launch(void* const* d_in, const int* in_sizes, int n_in,
                              void* d_out, int out_size)
{
    const float* X    = (const float*)d_in[0];
    const float* mask = (const float*)d_in[1];
    const float* Wq   = (const float*)d_in[2];
    const float* bq   = (const float*)d_in[3];
    const float* Wk   = (const float*)d_in[4];
    const float* bk   = (const float*)d_in[5];
    const float* Wv   = (const float*)d_in[6];
    const float* bv   = (const float*)d_in[7];
    float* out = (float*)d_out;
    (void)in_sizes; (void)n_in; (void)out_size;

    static int attr_done = 0;
    if (!attr_done) {
        cudaFuncSetAttribute(qkv_mma,  cudaFuncAttributeMaxDynamicSharedMemorySize, QKV_SMEM);
        cudaFuncSetAttribute(attn_mma, cudaFuncAttributeMaxDynamicSharedMemorySize, ATTN_SMEM);
        attr_done = 1;
    }

    dim3 g1(64, 12, 3);
    qkv_mma<<<g1, 256, QKV_SMEM>>>(X, Wq, bq, Wk, bk, Wv, bv);

    dim3 g2(S_ / 128, B_ * NH_);
    attn_mma<<<g2, 256, ATTN_SMEM>>>(mask, out);
}